// round 14
// baseline (speedup 1.0000x reference)
#include <cuda_runtime.h>
#include <cuda_fp16.h>
#include <mma.h>
#include <cstdint>
using namespace nvcuda;

#define NN 512
#define RST 516

// ---------------- device scratch (no allocations allowed) ----------------
__device__ __align__(16) float2 g_cg[2 * 512 * 512];   // (c, g) per rotation, padded slots
__device__ __align__(16) float  g_hc[2 * 512 * 512];   // h per rotation
__device__ float g_P[2 * 511 * 8];                     // per (mat,pivot,chunk) scale product
__device__ float g_U [NN * NN];
__device__ float g_Vs[NN * NN];
__device__ __align__(16) __half g_xh[32768 * 512];     // fp16 x
__device__ __align__(16) __half g_wh[NN * NN];
__device__ __align__(16) __half g_wl[NN * NN];

__device__ __forceinline__ uint32_t smem_u32(const void* p) {
    uint32_t a;
    asm("{ .reg .u64 t; cvta.to.shared.u64 t, %1; cvt.u32.u64 %0, t; }" : "=r"(a) : "l"(p));
    return a;
}
#define CP_ASYNC16(sa, gp) \
    asm volatile("cp.async.ca.shared.global [%0], [%1], 16;" :: "r"(sa), "l"(gp) : "memory")
#define CP_COMMIT() asm volatile("cp.async.commit_group;" ::: "memory")
#define CP_WAIT(n)  asm volatile("cp.async.wait_group %0;" :: "n"(n) : "memory")

// ---------------- 1) rotation coefficients (c,g,h,P) ----------------
// One thread per (mat, pivot, chunk). Chunk schedule identical to reconstruct.
// A = p*At with p = chunk-local prefix prod of c. g = s/p_{k+1}, h = s*p_k.
__global__ void setup_coef_kernel(const float* __restrict__ phiU,
                                  const float* __restrict__ phiV) {
    int t = blockIdx.x * blockDim.x + threadIdx.x;
    if (t >= 2 * 511 * 8) return;
    int mat = t / (511 * 8);
    int r   = t % (511 * 8);
    int i   = r >> 3;
    int w   = r & 7;
    int B   = (i >> 6) << 6;
    int LB  = 511 - B;
    int LC  = ((LB + 63) >> 6) << 3;
    int m0  = w * LC;
    int L   = 511 - i;
    const float* __restrict__ phi = mat ? phiV : phiU;
    long base = (long)mat * 262144 + (long)i * 512;
    float p = 1.0f;
    #pragma unroll 4
    for (int k = 0; k < LC; k++) {
        int m = m0 + k;
        float c = 1.0f, s = 0.0f;
        if (m < L) {
            int kk = i * 511 - (i * (i - 1)) / 2 + m;
            sincosf(__ldg(&phi[kk]), &s, &c);
        }
        float g = s / (p * c);
        float h = s * p;
        g_cg[base + m] = make_float2(c, g);
        g_hc[base + m] = h;
        p *= c;
    }
    g_P[((long)mat * 511 + i) * 8 + w] = p;
}

// ---------------- 1b) x -> fp16 ----------------
__global__ void xsplit_kernel(const float* __restrict__ x) {
    int i = (blockIdx.x * 256 + threadIdx.x) * 8;
    float4 v0 = *(const float4*)(x + i);
    float4 v1 = *(const float4*)(x + i + 4);
    __half h[8];
    #pragma unroll
    for (int e = 0; e < 8; e++) {
        float f = (e < 4) ? ((const float*)&v0)[e] : ((const float*)&v1)[e - 4];
        h[e] = __float2half_rn(f);
    }
    *(uint4*)(g_xh + i) = *(uint4*)h;
}

// ---------------- 2) Givens-mesh reconstruction, scaled coefficients ----------------
// Same verified skeleton as round 12/13 (fixed slices, register rows, 1 barrier
// per pivot); rotation math replaced by precomputed scaled coefficients:
//   phase1: D += g*u (plain sum; halves D0+D1)          [1 FMA/step]
//   stitch: A_out = P*A_in - P*(D0+D1)                  [Csh=P, Dsh=P*(D0+D1)]
//   phase2: u' = h*At + c*u ; At -= g*u ; A1 seed = A - D0   [3 ops/step]
template<int LC>
__device__ __forceinline__ void do_block(
    int B, int Bend, int w, int lane, int mat,
    float* __restrict__ myc, float2* __restrict__ cgring, float* __restrict__ hring,
    float* __restrict__ Csh, float* __restrict__ Dsh, float* __restrict__ A0sh)
{
    const int m0  = w * LC;
    const int fidx  = (m0 >> 1) + lane;     // cg float4 slice index
    const int fidxh = (m0 >> 2) + lane;     // h  float4 slice index
    const bool lact  = lane < (LC / 2);
    const bool lacth = lane < (LC / 4);
    const float4* cgf4 = (const float4*)(g_cg + (long)mat * 262144);  // 256 f4/pivot
    const float4* hf4  = (const float4*)(g_hc + (long)mat * 262144);  // 128 f4/pivot
    const float*  gP   = g_P + (long)mat * 511 * 8;

    float v[LC];
    #pragma unroll
    for (int k = 0; k < LC; k++) v[k] = myc[511 - m0 - k];

    float4 pcg, pcg2, phv, phv2;
    {
        float4* rw  = (float4*)(cgring + (B & 1) * 512);
        float4* rwh = (float4*)(hring + (B & 1) * 512);
        int i1 = (B + 1 <= 510) ? B + 1 : 510;
        int i2 = (B + 2 <= 510) ? B + 2 : 510;
        if (lact) {
            rw[fidx] = __ldg(cgf4 + B * 256 + fidx);
            pcg  = __ldg(cgf4 + i1 * 256 + fidx);
            pcg2 = __ldg(cgf4 + i2 * 256 + fidx);
        }
        if (lacth) {
            rwh[fidxh] = __ldg(hf4 + B * 128 + fidxh);
            phv  = __ldg(hf4 + i1 * 128 + fidxh);
            phv2 = __ldg(hf4 + i2 * 128 + fidxh);
        }
        __syncwarp();
    }

    for (int i = B; i < Bend; i++) {
        const int par = i & 1;
        const int L = 511 - i;
        const float4* rf  = (const float4*)(cgring + par * 512) + (m0 >> 1);
        const float2* hh2 = (const float2*)(hring + par * 512) + (m0 >> 1);
        const float P = __ldg(&gP[i * 8 + w]);

        if (i == B && w == 7) A0sh[par * 32 + lane] = myc[B];

        // ---- phase 1: D halves (plain sums of g*u) ----
        float D0 = 0.f, D1 = 0.f;
        #pragma unroll
        for (int q = 0; q < LC / 4; q++) {
            float4 r = rf[q];
            D0 = fmaf(r.y, v[2 * q], D0);
            D0 = fmaf(r.w, v[2 * q + 1], D0);
        }
        #pragma unroll
        for (int q = LC / 4; q < LC / 2; q++) {
            float4 r = rf[q];
            D1 = fmaf(r.y, v[2 * q], D1);
            D1 = fmaf(r.w, v[2 * q + 1], D1);
        }

        if (lane == 0) Csh[par * 8 + w] = P;
        Dsh[par * 256 + w * 32 + lane] = P * (D0 + D1);

        // stage next pivot's coefficient slices; refill from slice(i+3)
        if (i + 1 < Bend) {
            __syncwarp();
            float4* rw  = (float4*)(cgring + (par ^ 1) * 512);
            float4* rwh = (float4*)(hring + (par ^ 1) * 512);
            int nx = (i + 3 <= 510) ? i + 3 : 510;
            if (lact) {
                rw[fidx] = pcg;  pcg = pcg2;
                pcg2 = __ldg(cgf4 + nx * 256 + fidx);
            }
            if (lacth) {
                rwh[fidxh] = phv;  phv = phv2;
                phv2 = __ldg(hf4 + nx * 128 + fidxh);
            }
        }

        __syncthreads();                           // the one barrier: stitch

        float A = A0sh[par * 32 + lane];
        #pragma unroll 7
        for (int kk = 0; kk < w; kk++)
            A = fmaf(Csh[par * 8 + kk], A, -Dsh[par * 256 + kk * 32 + lane]);
        if (w == 7) myc[i] = fmaf(P, A, -(P * (D0 + D1)));   // final pivot value

        // ---- phase 2: apply; second half seeds At1 = A - D0 ----
        float At = A, At1 = A - D0;
        #pragma unroll
        for (int q = 0; q < LC / 4; q++) {
            float4 r = rf[q];
            float2 hh = hh2[q];
            { float u = v[2 * q];     float t = r.x * u;
              v[2 * q]     = fmaf(hh.x, At, t);  At = fmaf(-r.y, u, At); }
            { float u = v[2 * q + 1]; float t = r.z * u;
              v[2 * q + 1] = fmaf(hh.y, At, t);  At = fmaf(-r.w, u, At); }
        }
        #pragma unroll
        for (int q = LC / 4; q < LC / 2; q++) {
            float4 r = rf[q];
            float2 hh = hh2[q];
            { float u = v[2 * q];     float t = r.x * u;
              v[2 * q]     = fmaf(hh.x, At1, t); At1 = fmaf(-r.y, u, At1); }
            { float u = v[2 * q + 1]; float t = r.z * u;
              v[2 * q + 1] = fmaf(hh.y, At1, t); At1 = fmaf(-r.w, u, At1); }
        }

        // extract next pivot's A0 (row i+1 <-> m = L-1) from owner's registers
        if (i + 1 < Bend) {
            int idx = (L - 1) - m0;
            if (idx >= 0 && idx < LC) {
                float val = 0.f;
                #pragma unroll
                for (int k = 0; k < LC; k++) if (k == idx) val = v[k];
                A0sh[((i + 1) & 1) * 32 + lane] = val;
            }
        }
    }

    #pragma unroll
    for (int k = 0; k < LC; k++)
        if (m0 + k <= 511 - Bend) myc[511 - m0 - k] = v[k];
}

__global__ void __launch_bounds__(256) reconstruct_kernel(const float* __restrict__ dU,
                                                          const float* __restrict__ dV,
                                                          const float* __restrict__ sigma) {
    extern __shared__ float sm[];
    float*  cols   = sm;                        // 16512 floats
    float2* cgring = (float2*)(sm + 16512);     // 2 x 512 float2
    float*  hring  = sm + 16512 + 2048;         // 2 x 512 float
    float*  Csh    = sm + 19584;                // 2 x 8
    float*  Dsh    = sm + 19600;                // 2 x 8 x 32
    float*  A0sh   = sm + 20112;                // 2 x 32

    const int mat     = blockIdx.x >> 4;
    const int colbase = (blockIdx.x & 15) << 5;
    const int tid  = threadIdx.x;
    const int w    = tid >> 5;
    const int lane = tid & 31;
    const int col  = colbase + lane;

    float* myc = cols + lane * RST;

    for (int r = w * 64; r < w * 64 + 64; r += 4) {
        float4 z = make_float4(0.f, 0.f, 0.f, 0.f);
        if (col >= r && col < r + 4) ((float*)&z)[col - r] = 1.0f;
        *(float4*)&myc[r] = z;
    }

    for (int B = 0; B < 511; B += 64) {
        const int Bend = (B + 64 < 511) ? B + 64 : 511;
        const int LB = 511 - B;
        const int LC = ((LB + 63) >> 6) << 3;   // {64,56,48,40,32,24,16,8}
        __syncthreads();
        switch (LC) {
            case 64: do_block<64>(B, Bend, w, lane, mat, myc, cgring, hring, Csh, Dsh, A0sh); break;
            case 56: do_block<56>(B, Bend, w, lane, mat, myc, cgring, hring, Csh, Dsh, A0sh); break;
            case 48: do_block<48>(B, Bend, w, lane, mat, myc, cgring, hring, Csh, Dsh, A0sh); break;
            case 40: do_block<40>(B, Bend, w, lane, mat, myc, cgring, hring, Csh, Dsh, A0sh); break;
            case 32: do_block<32>(B, Bend, w, lane, mat, myc, cgring, hring, Csh, Dsh, A0sh); break;
            case 24: do_block<24>(B, Bend, w, lane, mat, myc, cgring, hring, Csh, Dsh, A0sh); break;
            case 16: do_block<16>(B, Bend, w, lane, mat, myc, cgring, hring, Csh, Dsh, A0sh); break;
            default: do_block< 8>(B, Bend, w, lane, mat, myc, cgring, hring, Csh, Dsh, A0sh); break;
        }
    }
    __syncthreads();

    if (mat == 0) {
        for (int r = w * 64; r < w * 64 + 64; r++)
            g_U[r * NN + col] = __ldg(&dU[r]) * myc[r];
    } else {
        for (int r = w * 64; r < w * 64 + 64; r++)
            g_Vs[r * NN + col] = __ldg(&sigma[r]) * __ldg(&dV[r]) * myc[r];
    }
}

// ---------------- 3) W = U @ Vs via 3-term fp16 wmma, split epilogue ----------------
// C[a][b] = sum_k U[a][k] * Vs[k][b]; U,Vs split to fp16 hi/lo in smem;
// acc = uh*vh + uh*vl + ul*vh (error ~5e-7). Epilogue splits W to fp16 hi/lo.
__global__ void __launch_bounds__(128) wgemm_kernel() {
    __shared__ __align__(16) char ws[20480];
    __half* uh = (__half*)ws;                 // [64][40]
    __half* ul = uh + 64 * 40;
    __half* vh = ul + 64 * 40;                // [32][72]
    __half* vl = vh + 32 * 72;

    const int tid  = threadIdx.x;
    const int warp = tid >> 5;
    const int a0 = blockIdx.y * 64;
    const int b0 = blockIdx.x * 64;
    const int wm = (warp >> 1) * 32;
    const int wn = (warp & 1) * 32;

    wmma::fragment<wmma::accumulator, 16, 16, 16, float> acc[2][2];
    #pragma unroll
    for (int i = 0; i < 2; i++)
        #pragma unroll
        for (int j = 0; j < 2; j++) wmma::fill_fragment(acc[i][j], 0.0f);

    for (int kt = 0; kt < NN; kt += 32) {
        // U tile 64x32: thread -> row tid/2, cols (tid&1)*16..+16
        {
            int row = tid >> 1, c0 = (tid & 1) * 16;
            const float* src = g_U + (size_t)(a0 + row) * NN + kt + c0;
            #pragma unroll
            for (int q = 0; q < 4; q++) {
                float4 f = *(const float4*)(src + q * 4);
                #pragma unroll
                for (int e = 0; e < 4; e++) {
                    float x = ((const float*)&f)[e];
                    __half h = __float2half_rn(x);
                    uh[row * 40 + c0 + q * 4 + e] = h;
                    ul[row * 40 + c0 + q * 4 + e] = __float2half_rn(x - __half2float(h));
                }
            }
        }
        // Vs tile 32x64: thread -> row tid/4, cols (tid&3)*16..+16
        {
            int row = tid >> 2, c0 = (tid & 3) * 16;
            const float* src = g_Vs + (size_t)(kt + row) * NN + b0 + c0;
            #pragma unroll
            for (int q = 0; q < 4; q++) {
                float4 f = *(const float4*)(src + q * 4);
                #pragma unroll
                for (int e = 0; e < 4; e++) {
                    float x = ((const float*)&f)[e];
                    __half h = __float2half_rn(x);
                    vh[row * 72 + c0 + q * 4 + e] = h;
                    vl[row * 72 + c0 + q * 4 + e] = __float2half_rn(x - __half2float(h));
                }
            }
        }
        __syncthreads();

        #pragma unroll
        for (int ks = 0; ks < 32; ks += 16) {
            wmma::fragment<wmma::matrix_a, 16, 16, 16, __half, wmma::row_major> ah[2], al[2];
            wmma::fragment<wmma::matrix_b, 16, 16, 16, __half, wmma::row_major> bh[2], bl[2];
            #pragma unroll
            for (int i = 0; i < 2; i++) {
                wmma::load_matrix_sync(ah[i], uh + (wm + i * 16) * 40 + ks, 40);
                wmma::load_matrix_sync(al[i], ul + (wm + i * 16) * 40 + ks, 40);
            }
            #pragma unroll
            for (int j = 0; j < 2; j++) {
                wmma::load_matrix_sync(bh[j], vh + ks * 72 + wn + j * 16, 72);
                wmma::load_matrix_sync(bl[j], vl + ks * 72 + wn + j * 16, 72);
            }
            #pragma unroll
            for (int i = 0; i < 2; i++)
                #pragma unroll
                for (int j = 0; j < 2; j++) {
                    wmma::mma_sync(acc[i][j], ah[i], bh[j], acc[i][j]);
                    wmma::mma_sync(acc[i][j], ah[i], bl[j], acc[i][j]);
                    wmma::mma_sync(acc[i][j], al[i], bh[j], acc[i][j]);
                }
        }
        __syncthreads();
    }

    // epilogue: stage fp32 in smem (reuse), split to g_wh/g_wl
    float* wsf = (float*)ws;   // [64][68]
    #pragma unroll
    for (int i = 0; i < 2; i++)
        #pragma unroll
        for (int j = 0; j < 2; j++)
            wmma::store_matrix_sync(wsf + (wm + i * 16) * 68 + wn + j * 16,
                                    acc[i][j], 68, wmma::mem_row_major);
    __syncthreads();
    for (int e = tid; e < 64 * 64; e += 128) {
        int rr = e >> 6, cc = e & 63;
        float x = wsf[rr * 68 + cc];
        __half h = __float2half_rn(x);
        g_wh[(size_t)(a0 + rr) * NN + b0 + cc] = h;
        g_wl[(size_t)(a0 + rr) * NN + b0 + cc] = __float2half_rn(x - __half2float(h));
    }
}

// ---------------- 4) out = x @ W^T, 2-term fp16 wmma, 3-stage cp.async ----------------
#define GBK 32
#define XLD 40
#define TILE_H (128 * XLD)
#define STAGE_H (3 * TILE_H)     // xh, wh, wl
#define NTILES (NN / GBK)

__global__ void __launch_bounds__(256, 2) hgemm_kernel(float* __restrict__ C) {
    __shared__ __half sbuf[3 * STAGE_H];

    const int tid  = threadIdx.x;
    const int warp = tid >> 5;
    const int m0 = blockIdx.y * 128;
    const int n0 = blockIdx.x * 128;
    const int wm = (warp >> 2) * 64;
    const int wn = (warp & 3) * 32;

    wmma::fragment<wmma::accumulator, 16, 16, 16, float> acc[4][2];
    #pragma unroll
    for (int i = 0; i < 4; i++)
        #pragma unroll
        for (int j = 0; j < 2; j++) wmma::fill_fragment(acc[i][j], 0.0f);

    const int lr = tid >> 1;
    const int lh = (tid & 1) * 16;
    const __half* gx[3];
    gx[0] = g_xh + (size_t)(m0 + lr) * NN + lh;
    gx[1] = g_wh + (size_t)(n0 + lr) * NN + lh;
    gx[2] = g_wl + (size_t)(n0 + lr) * NN + lh;
    const uint32_t sb0 = smem_u32(sbuf);
    const uint32_t dst_row = (uint32_t)(lr * XLD + lh) * 2;

    #define COPY_TILE(t, stg) do { \
        uint32_t _b = sb0 + (stg) * (STAGE_H * 2); \
        int _k = (t) * GBK; \
        _Pragma("unroll") \
        for (int _p = 0; _p < 3; _p++) { \
            uint32_t _d = _b + _p * (TILE_H * 2) + dst_row; \
            CP_ASYNC16(_d,      gx[_p] + _k); \
            CP_ASYNC16(_d + 16, gx[_p] + _k + 8); \
        } } while (0)

    COPY_TILE(0, 0); CP_COMMIT();
    COPY_TILE(1, 1); CP_COMMIT();

    for (int t = 0; t < NTILES; t++) {
        if (t + 2 < NTILES) { CP_WAIT(1); } else { CP_WAIT(0); }
        __syncthreads();

        const int stg = t % 3;
        const __half* xh = sbuf + stg * STAGE_H;
        const __half* wh = xh + TILE_H;
        const __half* wl = wh + TILE_H;

        #pragma unroll
        for (int ks = 0; ks < GBK; ks += 16) {
            wmma::fragment<wmma::matrix_a, 16, 16, 16, __half, wmma::row_major> ah[4];
            wmma::fragment<wmma::matrix_b, 16, 16, 16, __half, wmma::col_major> bh[2], bl[2];
            #pragma unroll
            for (int i = 0; i < 4; i++)
                wmma::load_matrix_sync(ah[i], xh + (wm + i * 16) * XLD + ks, XLD);
            #pragma unroll
            for (int j = 0; j < 2; j++) {
                wmma::load_matrix_sync(bh[j], wh + (wn + j * 16) * XLD + ks, XLD);
                wmma::load_matrix_sync(bl[j], wl + (wn + j * 16) * XLD + ks, XLD);
            }
            #pragma unroll
            for (int i = 0; i < 4; i++)
                #pragma unroll
                for (int j = 0; j < 2; j++) {
                    wmma::mma_sync(acc[i][j], ah[i], bh[j], acc[i][j]);
                    wmma::mma_sync(acc[i][j], ah[i], bl[j], acc[i][j]);
                }
        }

        if (t + 2 < NTILES) { COPY_TILE(t + 2, (t + 2) % 3); CP_COMMIT(); }
    }

    #pragma unroll
    for (int i = 0; i < 4; i++)
        #pragma unroll
        for (int j = 0; j < 2; j++)
            wmma::store_matrix_sync(&C[(size_t)(m0 + wm + i * 16) * NN + n0 + wn + j * 16],
                                    acc[i][j], NN, wmma::mem_row_major);
}

// ---------------- launch ----------------
extern "C" void kernel_launch(void* const* d_in, const int* in_sizes, int n_in,
                              void* d_out, int out_size) {
    const float* x     = (const float*)d_in[0];
    const float* phiU  = (const float*)d_in[1];
    const float* dU    = (const float*)d_in[2];
    const float* phiV  = (const float*)d_in[3];
    const float* dV    = (const float*)d_in[4];
    const float* sigma = (const float*)d_in[5];
    float* out = (float*)d_out;

    const int recon_smem = 20176 * 4;   // 80704 B
    cudaFuncSetAttribute(reconstruct_kernel,
                         cudaFuncAttributeMaxDynamicSharedMemorySize, recon_smem);

    setup_coef_kernel<<<(2 * 511 * 8 + 127) / 128, 128>>>(phiU, phiV);
    xsplit_kernel<<<32768 * 512 / (256 * 8), 256>>>(x);
    reconstruct_kernel<<<32, 256, recon_smem>>>(dU, dV, sigma);
    wgemm_kernel<<<dim3(8, 8), 128>>>();
    hgemm_kernel<<<dim3(NN / 128, 32768 / 128), 256>>>(out);
}

// round 15
// speedup vs baseline: 1.1186x; 1.1186x over previous
#include <cuda_runtime.h>
#include <cuda_fp16.h>
#include <mma.h>
#include <cstdint>
using namespace nvcuda;

#define NN 512
#define RST 516

// ---------------- device scratch (no allocations allowed) ----------------
__device__ __align__(16) float2 g_slot[2 * 512 * 512];   // 4 MB (c,s) padded slots
__device__ float g_U [NN * NN];
__device__ float g_Vs[NN * NN];
__device__ __align__(16) __half g_xh[32768 * 512];       // fp16 x
__device__ __align__(16) __half g_wh[NN * NN];
__device__ __align__(16) __half g_wl[NN * NN];

__device__ __forceinline__ uint32_t smem_u32(const void* p) {
    uint32_t a;
    asm("{ .reg .u64 t; cvta.to.shared.u64 t, %1; cvt.u32.u64 %0, t; }" : "=r"(a) : "l"(p));
    return a;
}
#define CP_ASYNC16(sa, gp) \
    asm volatile("cp.async.ca.shared.global [%0], [%1], 16;" :: "r"(sa), "l"(gp) : "memory")
#define CP_COMMIT() asm volatile("cp.async.commit_group;" ::: "memory")
#define CP_WAIT(n)  asm volatile("cp.async.wait_group %0;" :: "n"(n) : "memory")

// ---------------- 1) cos/sin precompute into padded slots ----------------
__global__ void setup_cs_kernel(const float* __restrict__ phiU,
                                const float* __restrict__ phiV) {
    int tid = blockIdx.x * blockDim.x + threadIdx.x;
    if (tid >= 2 * 512 * 512) return;
    int mat = tid >> 18;
    int r   = tid & 262143;
    int i   = r >> 9;
    int m   = r & 511;
    float c = 1.0f, s = 0.0f;
    if (m < 511 - i) {
        int k = i * 511 - (i * (i - 1)) / 2 + m;
        float ph = mat ? __ldg(&phiV[k]) : __ldg(&phiU[k]);
        sincosf(ph, &s, &c);
    }
    g_slot[tid] = make_float2(c, s);
}

// ---------------- 1b) x -> fp16 ----------------
__global__ void xsplit_kernel(const float* __restrict__ x) {
    int i = (blockIdx.x * 256 + threadIdx.x) * 8;
    float4 v0 = *(const float4*)(x + i);
    float4 v1 = *(const float4*)(x + i + 4);
    __half h[8];
    #pragma unroll
    for (int e = 0; e < 8; e++) {
        float f = (e < 4) ? ((const float*)&v0)[e] : ((const float*)&v1)[e - 4];
        h[e] = __float2half_rn(f);
    }
    *(uint4*)(g_xh + i) = *(uint4*)h;
}

// ---------------- 2) Givens-mesh reconstruction, 4-way interleaved chains ----------------
// Round-13 verified skeleton (fixed slices, register rows, 1 barrier/pivot,
// (c,s) ring). Chains split 4-way and manually interleaved for ILP-4 on the
// dependent FMAs. Quarters of the slice: [0,Q),[Q,2Q),[2Q,3Q),[3Q,4Q) float4
// iters (2 rotation steps each). Phase-2 carries seed from prefix folds.
template<int LC>
__device__ __forceinline__ void do_block(
    int B, int Bend, int w, int lane,
    float* __restrict__ myc, float2* __restrict__ ring0,
    float* __restrict__ Csh, float* __restrict__ Dsh, float* __restrict__ A0sh,
    const float4* __restrict__ slotf4)
{
    const int m0  = w * LC;
    const int f40 = m0 >> 1;
    const bool lact = lane < (LC / 2);
    const int fidx = f40 + lane;
    constexpr int Q = LC / 8;      // float4 iterations per quarter

    float v[LC];
    #pragma unroll
    for (int k = 0; k < LC; k++) v[k] = myc[511 - m0 - k];

    float4 pf, pf2;
    {
        float4* rw = (float4*)(ring0 + (B & 1) * 512);
        if (lact) {
            rw[fidx] = __ldg(slotf4 + B * 256 + fidx);
            int i1 = (B + 1 <= 510) ? B + 1 : 510;
            int i2 = (B + 2 <= 510) ? B + 2 : 510;
            pf  = __ldg(slotf4 + i1 * 256 + fidx);
            pf2 = __ldg(slotf4 + i2 * 256 + fidx);
        }
        __syncwarp();
    }

    for (int i = B; i < Bend; i++) {
        const int par = i & 1;
        const int L = 511 - i;
        const float4* rf = (const float4*)(ring0 + par * 512) + f40;

        if (i == B && w == 7) A0sh[par * 32 + lane] = myc[B];

        // ---- phase 1: four interleaved (C,D) chains ----
        float C0 = 1.f, D0 = 0.f, C1 = 1.f, D1 = 0.f;
        float C2 = 1.f, D2 = 0.f, C3 = 1.f, D3 = 0.f;
        #pragma unroll
        for (int q = 0; q < Q; q++) {
            float4 ra = rf[q], rb = rf[Q + q], rc = rf[2 * Q + q], rd = rf[3 * Q + q];
            D0 = fmaf(ra.x, D0, ra.y * v[2 * q]);               C0 *= ra.x;
            D1 = fmaf(rb.x, D1, rb.y * v[2 * (Q + q)]);         C1 *= rb.x;
            D2 = fmaf(rc.x, D2, rc.y * v[2 * (2 * Q + q)]);     C2 *= rc.x;
            D3 = fmaf(rd.x, D3, rd.y * v[2 * (3 * Q + q)]);     C3 *= rd.x;
            D0 = fmaf(ra.z, D0, ra.w * v[2 * q + 1]);           C0 *= ra.z;
            D1 = fmaf(rb.z, D1, rb.w * v[2 * (Q + q) + 1]);     C1 *= rb.z;
            D2 = fmaf(rc.z, D2, rc.w * v[2 * (2 * Q + q) + 1]); C2 *= rc.z;
            D3 = fmaf(rd.z, D3, rd.w * v[2 * (3 * Q + q) + 1]); C3 *= rd.z;
        }
        const float C01 = C0 * C1, D01 = fmaf(C1, D0, D1);
        const float C23 = C2 * C3, D23 = fmaf(C3, D2, D3);
        const float Cw = C01 * C23;
        const float Dw = fmaf(C23, D01, D23);

        if (lane == 0) Csh[par * 8 + w] = Cw;
        Dsh[par * 256 + w * 32 + lane] = Dw;

        // stage next pivot's cs slice; refill pf2 from slice(i+3)
        if (i + 1 < Bend) {
            __syncwarp();
            float4* rw = (float4*)(ring0 + (par ^ 1) * 512);
            if (lact) {
                rw[fidx] = pf;
                pf = pf2;
                int nx = (i + 3 <= 510) ? i + 3 : 510;
                pf2 = __ldg(slotf4 + nx * 256 + fidx);
            }
        }

        __syncthreads();                           // the one barrier: stitch

        float A = A0sh[par * 32 + lane];
        #pragma unroll 7
        for (int kk = 0; kk < w; kk++)
            A = fmaf(Csh[par * 8 + kk], A, -Dsh[par * 256 + kk * 32 + lane]);
        if (w == 7) myc[i] = fmaf(Cw, A, -Dw);     // final pivot value

        // ---- phase 2: four interleaved carries, seeded from prefix folds ----
        float A0c = A;
        float A1c = fmaf(C0, A, -D0);
        float A2c = fmaf(C01, A, -D01);
        const float C012 = C01 * C2;
        const float D012 = fmaf(C2, D01, D2);
        float A3c = fmaf(C012, A, -D012);
        #pragma unroll
        for (int q = 0; q < Q; q++) {
            float4 ra = rf[q], rb = rf[Q + q], rc = rf[2 * Q + q], rd = rf[3 * Q + q];
            { float u = v[2 * q];               float t = ra.y * u;
              v[2 * q]               = fmaf(ra.y, A0c, ra.x * u); A0c = fmaf(ra.x, A0c, -t); }
            { float u = v[2 * (Q + q)];         float t = rb.y * u;
              v[2 * (Q + q)]         = fmaf(rb.y, A1c, rb.x * u); A1c = fmaf(rb.x, A1c, -t); }
            { float u = v[2 * (2 * Q + q)];     float t = rc.y * u;
              v[2 * (2 * Q + q)]     = fmaf(rc.y, A2c, rc.x * u); A2c = fmaf(rc.x, A2c, -t); }
            { float u = v[2 * (3 * Q + q)];     float t = rd.y * u;
              v[2 * (3 * Q + q)]     = fmaf(rd.y, A3c, rd.x * u); A3c = fmaf(rd.x, A3c, -t); }
            { float u = v[2 * q + 1];           float t = ra.w * u;
              v[2 * q + 1]           = fmaf(ra.w, A0c, ra.z * u); A0c = fmaf(ra.z, A0c, -t); }
            { float u = v[2 * (Q + q) + 1];     float t = rb.w * u;
              v[2 * (Q + q) + 1]     = fmaf(rb.w, A1c, rb.z * u); A1c = fmaf(rb.z, A1c, -t); }
            { float u = v[2 * (2 * Q + q) + 1]; float t = rc.w * u;
              v[2 * (2 * Q + q) + 1] = fmaf(rc.w, A2c, rc.z * u); A2c = fmaf(rc.z, A2c, -t); }
            { float u = v[2 * (3 * Q + q) + 1]; float t = rd.w * u;
              v[2 * (3 * Q + q) + 1] = fmaf(rd.w, A3c, rd.z * u); A3c = fmaf(rd.z, A3c, -t); }
        }

        // extract next pivot's A0 (row i+1 <-> m = L-1) from owner's registers
        if (i + 1 < Bend) {
            int idx = (L - 1) - m0;
            if (idx >= 0 && idx < LC) {
                float val = 0.f;
                #pragma unroll
                for (int k = 0; k < LC; k++) if (k == idx) val = v[k];
                A0sh[((i + 1) & 1) * 32 + lane] = val;
            }
        }
    }

    #pragma unroll
    for (int k = 0; k < LC; k++)
        if (m0 + k <= 511 - Bend) myc[511 - m0 - k] = v[k];
}

__global__ void __launch_bounds__(256) reconstruct_kernel(const float* __restrict__ dU,
                                                          const float* __restrict__ dV,
                                                          const float* __restrict__ sigma) {
    extern __shared__ float sm[];
    float*  cols  = sm;
    float2* ring0 = (float2*)(sm + 32 * RST);
    float*  Csh   = (float*)(ring0 + 1024);
    float*  Dsh   = Csh + 16;
    float*  A0sh  = Dsh + 512;

    const int mat     = blockIdx.x >> 4;
    const int colbase = (blockIdx.x & 15) << 5;
    const int tid  = threadIdx.x;
    const int w    = tid >> 5;
    const int lane = tid & 31;
    const int col  = colbase + lane;

    const float4* slotf4 = (const float4*)(g_slot + mat * 262144);
    float* myc = cols + lane * RST;

    for (int r = w * 64; r < w * 64 + 64; r += 4) {
        float4 z = make_float4(0.f, 0.f, 0.f, 0.f);
        if (col >= r && col < r + 4) ((float*)&z)[col - r] = 1.0f;
        *(float4*)&myc[r] = z;
    }

    for (int B = 0; B < 511; B += 64) {
        const int Bend = (B + 64 < 511) ? B + 64 : 511;
        const int LB = 511 - B;
        const int LC = ((LB + 63) >> 6) << 3;   // {64,56,48,40,32,24,16,8}
        __syncthreads();
        switch (LC) {
            case 64: do_block<64>(B, Bend, w, lane, myc, ring0, Csh, Dsh, A0sh, slotf4); break;
            case 56: do_block<56>(B, Bend, w, lane, myc, ring0, Csh, Dsh, A0sh, slotf4); break;
            case 48: do_block<48>(B, Bend, w, lane, myc, ring0, Csh, Dsh, A0sh, slotf4); break;
            case 40: do_block<40>(B, Bend, w, lane, myc, ring0, Csh, Dsh, A0sh, slotf4); break;
            case 32: do_block<32>(B, Bend, w, lane, myc, ring0, Csh, Dsh, A0sh, slotf4); break;
            case 24: do_block<24>(B, Bend, w, lane, myc, ring0, Csh, Dsh, A0sh, slotf4); break;
            case 16: do_block<16>(B, Bend, w, lane, myc, ring0, Csh, Dsh, A0sh, slotf4); break;
            default: do_block< 8>(B, Bend, w, lane, myc, ring0, Csh, Dsh, A0sh, slotf4); break;
        }
    }
    __syncthreads();

    if (mat == 0) {
        for (int r = w * 64; r < w * 64 + 64; r++)
            g_U[r * NN + col] = __ldg(&dU[r]) * myc[r];
    } else {
        for (int r = w * 64; r < w * 64 + 64; r++)
            g_Vs[r * NN + col] = __ldg(&sigma[r]) * __ldg(&dV[r]) * myc[r];
    }
}

// ---------------- 3) W = U @ Vs via 3-term fp16 wmma, split epilogue ----------------
__global__ void __launch_bounds__(128) wgemm_kernel() {
    __shared__ __align__(16) char ws[20480];
    __half* uh = (__half*)ws;                 // [64][40]
    __half* ul = uh + 64 * 40;
    __half* vh = ul + 64 * 40;                // [32][72]
    __half* vl = vh + 32 * 72;

    const int tid  = threadIdx.x;
    const int warp = tid >> 5;
    const int a0 = blockIdx.y * 64;
    const int b0 = blockIdx.x * 64;
    const int wm = (warp >> 1) * 32;
    const int wn = (warp & 1) * 32;

    wmma::fragment<wmma::accumulator, 16, 16, 16, float> acc[2][2];
    #pragma unroll
    for (int i = 0; i < 2; i++)
        #pragma unroll
        for (int j = 0; j < 2; j++) wmma::fill_fragment(acc[i][j], 0.0f);

    for (int kt = 0; kt < NN; kt += 32) {
        {
            int row = tid >> 1, c0 = (tid & 1) * 16;
            const float* src = g_U + (size_t)(a0 + row) * NN + kt + c0;
            #pragma unroll
            for (int q = 0; q < 4; q++) {
                float4 f = *(const float4*)(src + q * 4);
                #pragma unroll
                for (int e = 0; e < 4; e++) {
                    float x = ((const float*)&f)[e];
                    __half h = __float2half_rn(x);
                    uh[row * 40 + c0 + q * 4 + e] = h;
                    ul[row * 40 + c0 + q * 4 + e] = __float2half_rn(x - __half2float(h));
                }
            }
        }
        {
            int row = tid >> 2, c0 = (tid & 3) * 16;
            const float* src = g_Vs + (size_t)(kt + row) * NN + b0 + c0;
            #pragma unroll
            for (int q = 0; q < 4; q++) {
                float4 f = *(const float4*)(src + q * 4);
                #pragma unroll
                for (int e = 0; e < 4; e++) {
                    float x = ((const float*)&f)[e];
                    __half h = __float2half_rn(x);
                    vh[row * 72 + c0 + q * 4 + e] = h;
                    vl[row * 72 + c0 + q * 4 + e] = __float2half_rn(x - __half2float(h));
                }
            }
        }
        __syncthreads();

        #pragma unroll
        for (int ks = 0; ks < 32; ks += 16) {
            wmma::fragment<wmma::matrix_a, 16, 16, 16, __half, wmma::row_major> ah[2], al[2];
            wmma::fragment<wmma::matrix_b, 16, 16, 16, __half, wmma::row_major> bh[2], bl[2];
            #pragma unroll
            for (int i = 0; i < 2; i++) {
                wmma::load_matrix_sync(ah[i], uh + (wm + i * 16) * 40 + ks, 40);
                wmma::load_matrix_sync(al[i], ul + (wm + i * 16) * 40 + ks, 40);
            }
            #pragma unroll
            for (int j = 0; j < 2; j++) {
                wmma::load_matrix_sync(bh[j], vh + ks * 72 + wn + j * 16, 72);
                wmma::load_matrix_sync(bl[j], vl + ks * 72 + wn + j * 16, 72);
            }
            #pragma unroll
            for (int i = 0; i < 2; i++)
                #pragma unroll
                for (int j = 0; j < 2; j++) {
                    wmma::mma_sync(acc[i][j], ah[i], bh[j], acc[i][j]);
                    wmma::mma_sync(acc[i][j], ah[i], bl[j], acc[i][j]);
                    wmma::mma_sync(acc[i][j], al[i], bh[j], acc[i][j]);
                }
        }
        __syncthreads();
    }

    float* wsf = (float*)ws;   // [64][68]
    #pragma unroll
    for (int i = 0; i < 2; i++)
        #pragma unroll
        for (int j = 0; j < 2; j++)
            wmma::store_matrix_sync(wsf + (wm + i * 16) * 68 + wn + j * 16,
                                    acc[i][j], 68, wmma::mem_row_major);
    __syncthreads();
    for (int e = tid; e < 64 * 64; e += 128) {
        int rr = e >> 6, cc = e & 63;
        float x = wsf[rr * 68 + cc];
        __half h = __float2half_rn(x);
        g_wh[(size_t)(a0 + rr) * NN + b0 + cc] = h;
        g_wl[(size_t)(a0 + rr) * NN + b0 + cc] = __float2half_rn(x - __half2float(h));
    }
}

// ---------------- 4) out = x @ W^T, 2-term fp16 wmma, cp.async pipeline ----------------
#define GBK 32
#define XLD 40
#define TILE_H (128 * XLD)
#define STAGE_H (3 * TILE_H)     // xh, wh, wl

__global__ void __launch_bounds__(256, 2) hgemm_kernel(float* __restrict__ C) {
    __shared__ __half sbuf[2 * STAGE_H];

    const int tid  = threadIdx.x;
    const int warp = tid >> 5;
    const int m0 = blockIdx.y * 128;
    const int n0 = blockIdx.x * 128;
    const int wm = (warp >> 2) * 64;
    const int wn = (warp & 3) * 32;

    wmma::fragment<wmma::accumulator, 16, 16, 16, float> acc[4][2];
    #pragma unroll
    for (int i = 0; i < 4; i++)
        #pragma unroll
        for (int j = 0; j < 2; j++) wmma::fill_fragment(acc[i][j], 0.0f);

    const int lr = tid >> 1;
    const int lh = (tid & 1) * 16;
    const __half* gx[3];
    gx[0] = g_xh + (size_t)(m0 + lr) * NN + lh;
    gx[1] = g_wh + (size_t)(n0 + lr) * NN + lh;
    gx[2] = g_wl + (size_t)(n0 + lr) * NN + lh;
    const uint32_t sb0 = smem_u32(sbuf);
    const uint32_t dst_row = (uint32_t)(lr * XLD + lh) * 2;

    #define COPY_TILE(t, stg) do { \
        uint32_t _b = sb0 + (stg) * (STAGE_H * 2); \
        int _k = (t) * GBK; \
        _Pragma("unroll") \
        for (int _p = 0; _p < 3; _p++) { \
            uint32_t _d = _b + _p * (TILE_H * 2) + dst_row; \
            CP_ASYNC16(_d,      gx[_p] + _k); \
            CP_ASYNC16(_d + 16, gx[_p] + _k + 8); \
        } } while (0)

    COPY_TILE(0, 0);
    CP_COMMIT();

    for (int t = 0; t < NN / GBK; t++) {
        const int cur = t & 1;
        if (t + 1 < NN / GBK) { COPY_TILE(t + 1, cur ^ 1); CP_COMMIT(); CP_WAIT(1); }
        else                  { CP_WAIT(0); }
        __syncthreads();

        const __half* xh = sbuf + cur * STAGE_H;
        const __half* wh = xh + TILE_H;
        const __half* wl = wh + TILE_H;

        #pragma unroll
        for (int ks = 0; ks < GBK; ks += 16) {
            wmma::fragment<wmma::matrix_a, 16, 16, 16, __half, wmma::row_major> ah[4];
            wmma::fragment<wmma::matrix_b, 16, 16, 16, __half, wmma::col_major> bh[2], bl[2];
            #pragma unroll
            for (int i = 0; i < 4; i++)
                wmma::load_matrix_sync(ah[i], xh + (wm + i * 16) * XLD + ks, XLD);
            #pragma unroll
            for (int j = 0; j < 2; j++) {
                wmma::load_matrix_sync(bh[j], wh + (wn + j * 16) * XLD + ks, XLD);
                wmma::load_matrix_sync(bl[j], wl + (wn + j * 16) * XLD + ks, XLD);
            }
            #pragma unroll
            for (int i = 0; i < 4; i++)
                #pragma unroll
                for (int j = 0; j < 2; j++) {
                    wmma::mma_sync(acc[i][j], ah[i], bh[j], acc[i][j]);
                    wmma::mma_sync(acc[i][j], ah[i], bl[j], acc[i][j]);
                }
        }
        __syncthreads();
    }

    #pragma unroll
    for (int i = 0; i < 4; i++)
        #pragma unroll
        for (int j = 0; j < 2; j++)
            wmma::store_matrix_sync(&C[(size_t)(m0 + wm + i * 16) * NN + n0 + wn + j * 16],
                                    acc[i][j], NN, wmma::mem_row_major);
}

// ---------------- launch ----------------
extern "C" void kernel_launch(void* const* d_in, const int* in_sizes, int n_in,
                              void* d_out, int out_size) {
    const float* x     = (const float*)d_in[0];
    const float* phiU  = (const float*)d_in[1];
    const float* dU    = (const float*)d_in[2];
    const float* phiV  = (const float*)d_in[3];
    const float* dV    = (const float*)d_in[4];
    const float* sigma = (const float*)d_in[5];
    float* out = (float*)d_out;

    const int recon_smem = 32 * RST * 4 + 1024 * 8 + (16 + 512 + 64) * 4;
    cudaFuncSetAttribute(reconstruct_kernel,
                         cudaFuncAttributeMaxDynamicSharedMemorySize, recon_smem);

    setup_cs_kernel<<<(2 * 512 * 512 + 255) / 256, 256>>>(phiU, phiV);
    xsplit_kernel<<<32768 * 512 / (256 * 8), 256>>>(x);
    reconstruct_kernel<<<32, 256, recon_smem>>>(dU, dV, sigma);
    wgemm_kernel<<<dim3(8, 8), 128>>>();
    hgemm_kernel<<<dim3(NN / 128, 32768 / 128), 256>>>(out);
}

// round 16
// speedup vs baseline: 1.1436x; 1.0223x over previous
#include <cuda_runtime.h>
#include <cuda_fp16.h>
#include <mma.h>
#include <cstdint>
using namespace nvcuda;

#define NN 512
#define RST 516

// ---------------- device scratch (no allocations allowed) ----------------
__device__ __align__(16) float2 g_slot[2 * 512 * 512];   // (c,s) padded slots
__device__ __align__(16) float4 g_Cq[2 * 511 * 8];       // per (mat,pivot,warp) quarter cos-products
__device__ float g_U [NN * NN];
__device__ float g_Vs[NN * NN];
__device__ __align__(16) __half g_xh[32768 * 512];       // fp16 x
__device__ __align__(16) __half g_wh[NN * NN];           // fp16 W

__device__ __forceinline__ uint32_t smem_u32(const void* p) {
    uint32_t a;
    asm("{ .reg .u64 t; cvta.to.shared.u64 t, %1; cvt.u32.u64 %0, t; }" : "=r"(a) : "l"(p));
    return a;
}
#define CP_ASYNC16(sa, gp) \
    asm volatile("cp.async.ca.shared.global [%0], [%1], 16;" :: "r"(sa), "l"(gp) : "memory")
#define CP_COMMIT() asm volatile("cp.async.commit_group;" ::: "memory")
#define CP_WAIT(n)  asm volatile("cp.async.wait_group %0;" :: "n"(n) : "memory")

// ---------------- 1) cos/sin precompute into padded slots ----------------
__global__ void setup_cs_kernel(const float* __restrict__ phiU,
                                const float* __restrict__ phiV) {
    int tid = blockIdx.x * blockDim.x + threadIdx.x;
    if (tid >= 2 * 512 * 512) return;
    int mat = tid >> 18;
    int r   = tid & 262143;
    int i   = r >> 9;
    int m   = r & 511;
    float c = 1.0f, s = 0.0f;
    if (m < 511 - i) {
        int k = i * 511 - (i * (i - 1)) / 2 + m;
        float ph = mat ? __ldg(&phiV[k]) : __ldg(&phiU[k]);
        sincosf(ph, &s, &c);
    }
    g_slot[tid] = make_float2(c, s);
}

// ---------------- 1a) per-(pivot,warp) quarter cos-products ----------------
__global__ void setup_cq_kernel() {
    int t = blockIdx.x * blockDim.x + threadIdx.x;
    if (t >= 2 * 511 * 8) return;
    int mat = t / (511 * 8);
    int r   = t % (511 * 8);
    int i   = r >> 3;
    int w   = r & 7;
    int B   = (i >> 6) << 6;
    int LC  = ((511 - B + 63) >> 6) << 3;
    int m0  = w * LC;
    const float2* base = g_slot + (long)mat * 262144 + (long)i * 512 + m0;
    float4 c4;
    #pragma unroll
    for (int qt = 0; qt < 4; qt++) {
        float p = 1.0f;
        for (int k = qt * (LC / 4); k < (qt + 1) * (LC / 4); k++)
            p *= __ldg(&base[k]).x;
        ((float*)&c4)[qt] = p;
    }
    g_Cq[t] = c4;
}

// ---------------- 1b) x -> fp16 ----------------
__global__ void xsplit_kernel(const float* __restrict__ x) {
    int i = (blockIdx.x * 256 + threadIdx.x) * 8;
    float4 v0 = *(const float4*)(x + i);
    float4 v1 = *(const float4*)(x + i + 4);
    __half h[8];
    #pragma unroll
    for (int e = 0; e < 8; e++) {
        float f = (e < 4) ? ((const float*)&v0)[e] : ((const float*)&v1)[e - 4];
        h[e] = __float2half_rn(f);
    }
    *(uint4*)(g_xh + i) = *(uint4*)h;
}

// ---------------- 2) Givens-mesh reconstruction, 4-way interleaved chains ----------------
// Round-15 verified skeleton; phase-1 C-mul chain replaced by precomputed
// quarter cos-products (one __ldg float4 per pivot per warp).
template<int LC>
__device__ __forceinline__ void do_block(
    int B, int Bend, int w, int lane,
    float* __restrict__ myc, float2* __restrict__ ring0,
    float* __restrict__ Csh, float* __restrict__ Dsh, float* __restrict__ A0sh,
    const float4* __restrict__ slotf4, const float4* __restrict__ gCq)
{
    const int m0  = w * LC;
    const int f40 = m0 >> 1;
    const bool lact = lane < (LC / 2);
    const int fidx = f40 + lane;
    constexpr int Q = LC / 8;      // float4 iterations per quarter

    float v[LC];
    #pragma unroll
    for (int k = 0; k < LC; k++) v[k] = myc[511 - m0 - k];

    float4 pf, pf2;
    {
        float4* rw = (float4*)(ring0 + (B & 1) * 512);
        if (lact) {
            rw[fidx] = __ldg(slotf4 + B * 256 + fidx);
            int i1 = (B + 1 <= 510) ? B + 1 : 510;
            int i2 = (B + 2 <= 510) ? B + 2 : 510;
            pf  = __ldg(slotf4 + i1 * 256 + fidx);
            pf2 = __ldg(slotf4 + i2 * 256 + fidx);
        }
        __syncwarp();
    }

    for (int i = B; i < Bend; i++) {
        const int par = i & 1;
        const int L = 511 - i;
        const float4* rf = (const float4*)(ring0 + par * 512) + f40;
        const float4 cq = __ldg(&gCq[i * 8 + w]);   // C0,C1,C2,C3

        if (i == B && w == 7) A0sh[par * 32 + lane] = myc[B];

        // ---- phase 1: four interleaved D chains (C from table) ----
        float D0 = 0.f, D1 = 0.f, D2 = 0.f, D3 = 0.f;
        #pragma unroll
        for (int q = 0; q < Q; q++) {
            float4 ra = rf[q], rb = rf[Q + q], rc = rf[2 * Q + q], rd = rf[3 * Q + q];
            D0 = fmaf(ra.x, D0, ra.y * v[2 * q]);
            D1 = fmaf(rb.x, D1, rb.y * v[2 * (Q + q)]);
            D2 = fmaf(rc.x, D2, rc.y * v[2 * (2 * Q + q)]);
            D3 = fmaf(rd.x, D3, rd.y * v[2 * (3 * Q + q)]);
            D0 = fmaf(ra.z, D0, ra.w * v[2 * q + 1]);
            D1 = fmaf(rb.z, D1, rb.w * v[2 * (Q + q) + 1]);
            D2 = fmaf(rc.z, D2, rc.w * v[2 * (2 * Q + q) + 1]);
            D3 = fmaf(rd.z, D3, rd.w * v[2 * (3 * Q + q) + 1]);
        }
        const float C0 = cq.x, C1 = cq.y, C2 = cq.z, C3 = cq.w;
        const float C01 = C0 * C1, D01 = fmaf(C1, D0, D1);
        const float C23 = C2 * C3, D23 = fmaf(C3, D2, D3);
        const float Cw = C01 * C23;
        const float Dw = fmaf(C23, D01, D23);

        if (lane == 0) Csh[par * 8 + w] = Cw;
        Dsh[par * 256 + w * 32 + lane] = Dw;

        // stage next pivot's cs slice; refill pf2 from slice(i+3)
        if (i + 1 < Bend) {
            __syncwarp();
            float4* rw = (float4*)(ring0 + (par ^ 1) * 512);
            if (lact) {
                rw[fidx] = pf;
                pf = pf2;
                int nx = (i + 3 <= 510) ? i + 3 : 510;
                pf2 = __ldg(slotf4 + nx * 256 + fidx);
            }
        }

        __syncthreads();                           // the one barrier: stitch

        float A = A0sh[par * 32 + lane];
        #pragma unroll 7
        for (int kk = 0; kk < w; kk++)
            A = fmaf(Csh[par * 8 + kk], A, -Dsh[par * 256 + kk * 32 + lane]);
        if (w == 7) myc[i] = fmaf(Cw, A, -Dw);     // final pivot value

        // ---- phase 2: four interleaved carries, seeded from prefix folds ----
        float A0c = A;
        float A1c = fmaf(C0, A, -D0);
        float A2c = fmaf(C01, A, -D01);
        const float C012 = C01 * C2;
        const float D012 = fmaf(C2, D01, D2);
        float A3c = fmaf(C012, A, -D012);
        #pragma unroll
        for (int q = 0; q < Q; q++) {
            float4 ra = rf[q], rb = rf[Q + q], rc = rf[2 * Q + q], rd = rf[3 * Q + q];
            { float u = v[2 * q];               float t = ra.y * u;
              v[2 * q]               = fmaf(ra.y, A0c, ra.x * u); A0c = fmaf(ra.x, A0c, -t); }
            { float u = v[2 * (Q + q)];         float t = rb.y * u;
              v[2 * (Q + q)]         = fmaf(rb.y, A1c, rb.x * u); A1c = fmaf(rb.x, A1c, -t); }
            { float u = v[2 * (2 * Q + q)];     float t = rc.y * u;
              v[2 * (2 * Q + q)]     = fmaf(rc.y, A2c, rc.x * u); A2c = fmaf(rc.x, A2c, -t); }
            { float u = v[2 * (3 * Q + q)];     float t = rd.y * u;
              v[2 * (3 * Q + q)]     = fmaf(rd.y, A3c, rd.x * u); A3c = fmaf(rd.x, A3c, -t); }
            { float u = v[2 * q + 1];           float t = ra.w * u;
              v[2 * q + 1]           = fmaf(ra.w, A0c, ra.z * u); A0c = fmaf(ra.z, A0c, -t); }
            { float u = v[2 * (Q + q) + 1];     float t = rb.w * u;
              v[2 * (Q + q) + 1]     = fmaf(rb.w, A1c, rb.z * u); A1c = fmaf(rb.z, A1c, -t); }
            { float u = v[2 * (2 * Q + q) + 1]; float t = rc.w * u;
              v[2 * (2 * Q + q) + 1] = fmaf(rc.w, A2c, rc.z * u); A2c = fmaf(rc.z, A2c, -t); }
            { float u = v[2 * (3 * Q + q) + 1]; float t = rd.w * u;
              v[2 * (3 * Q + q) + 1] = fmaf(rd.w, A3c, rd.z * u); A3c = fmaf(rd.z, A3c, -t); }
        }

        // extract next pivot's A0 (row i+1 <-> m = L-1) from owner's registers
        if (i + 1 < Bend) {
            int idx = (L - 1) - m0;
            if (idx >= 0 && idx < LC) {
                float val = 0.f;
                #pragma unroll
                for (int k = 0; k < LC; k++) if (k == idx) val = v[k];
                A0sh[((i + 1) & 1) * 32 + lane] = val;
            }
        }
    }

    #pragma unroll
    for (int k = 0; k < LC; k++)
        if (m0 + k <= 511 - Bend) myc[511 - m0 - k] = v[k];
}

__global__ void __launch_bounds__(256) reconstruct_kernel(const float* __restrict__ dU,
                                                          const float* __restrict__ dV,
                                                          const float* __restrict__ sigma) {
    extern __shared__ float sm[];
    float*  cols  = sm;
    float2* ring0 = (float2*)(sm + 32 * RST);
    float*  Csh   = (float*)(ring0 + 1024);
    float*  Dsh   = Csh + 16;
    float*  A0sh  = Dsh + 512;

    const int mat     = blockIdx.x >> 4;
    const int colbase = (blockIdx.x & 15) << 5;
    const int tid  = threadIdx.x;
    const int w    = tid >> 5;
    const int lane = tid & 31;
    const int col  = colbase + lane;

    const float4* slotf4 = (const float4*)(g_slot + mat * 262144);
    const float4* gCq    = g_Cq + (long)mat * 511 * 8;
    float* myc = cols + lane * RST;

    for (int r = w * 64; r < w * 64 + 64; r += 4) {
        float4 z = make_float4(0.f, 0.f, 0.f, 0.f);
        if (col >= r && col < r + 4) ((float*)&z)[col - r] = 1.0f;
        *(float4*)&myc[r] = z;
    }

    for (int B = 0; B < 511; B += 64) {
        const int Bend = (B + 64 < 511) ? B + 64 : 511;
        const int LB = 511 - B;
        const int LC = ((LB + 63) >> 6) << 3;   // {64,56,48,40,32,24,16,8}
        __syncthreads();
        switch (LC) {
            case 64: do_block<64>(B, Bend, w, lane, myc, ring0, Csh, Dsh, A0sh, slotf4, gCq); break;
            case 56: do_block<56>(B, Bend, w, lane, myc, ring0, Csh, Dsh, A0sh, slotf4, gCq); break;
            case 48: do_block<48>(B, Bend, w, lane, myc, ring0, Csh, Dsh, A0sh, slotf4, gCq); break;
            case 40: do_block<40>(B, Bend, w, lane, myc, ring0, Csh, Dsh, A0sh, slotf4, gCq); break;
            case 32: do_block<32>(B, Bend, w, lane, myc, ring0, Csh, Dsh, A0sh, slotf4, gCq); break;
            case 24: do_block<24>(B, Bend, w, lane, myc, ring0, Csh, Dsh, A0sh, slotf4, gCq); break;
            case 16: do_block<16>(B, Bend, w, lane, myc, ring0, Csh, Dsh, A0sh, slotf4, gCq); break;
            default: do_block< 8>(B, Bend, w, lane, myc, ring0, Csh, Dsh, A0sh, slotf4, gCq); break;
        }
    }
    __syncthreads();

    if (mat == 0) {
        for (int r = w * 64; r < w * 64 + 64; r++)
            g_U[r * NN + col] = __ldg(&dU[r]) * myc[r];
    } else {
        for (int r = w * 64; r < w * 64 + 64; r++)
            g_Vs[r * NN + col] = __ldg(&sigma[r]) * __ldg(&dV[r]) * myc[r];
    }
}

// ---------------- 3) W = U @ Vs via 3-term fp16 wmma, fp16 epilogue ----------------
__global__ void __launch_bounds__(128) wgemm_kernel() {
    __shared__ __align__(16) char ws[20480];
    __half* uh = (__half*)ws;                 // [64][40]
    __half* ul = uh + 64 * 40;
    __half* vh = ul + 64 * 40;                // [32][72]
    __half* vl = vh + 32 * 72;

    const int tid  = threadIdx.x;
    const int warp = tid >> 5;
    const int a0 = blockIdx.y * 64;
    const int b0 = blockIdx.x * 64;
    const int wm = (warp >> 1) * 32;
    const int wn = (warp & 1) * 32;

    wmma::fragment<wmma::accumulator, 16, 16, 16, float> acc[2][2];
    #pragma unroll
    for (int i = 0; i < 2; i++)
        #pragma unroll
        for (int j = 0; j < 2; j++) wmma::fill_fragment(acc[i][j], 0.0f);

    for (int kt = 0; kt < NN; kt += 32) {
        {
            int row = tid >> 1, c0 = (tid & 1) * 16;
            const float* src = g_U + (size_t)(a0 + row) * NN + kt + c0;
            #pragma unroll
            for (int q = 0; q < 4; q++) {
                float4 f = *(const float4*)(src + q * 4);
                #pragma unroll
                for (int e = 0; e < 4; e++) {
                    float x = ((const float*)&f)[e];
                    __half h = __float2half_rn(x);
                    uh[row * 40 + c0 + q * 4 + e] = h;
                    ul[row * 40 + c0 + q * 4 + e] = __float2half_rn(x - __half2float(h));
                }
            }
        }
        {
            int row = tid >> 2, c0 = (tid & 3) * 16;
            const float* src = g_Vs + (size_t)(kt + row) * NN + b0 + c0;
            #pragma unroll
            for (int q = 0; q < 4; q++) {
                float4 f = *(const float4*)(src + q * 4);
                #pragma unroll
                for (int e = 0; e < 4; e++) {
                    float x = ((const float*)&f)[e];
                    __half h = __float2half_rn(x);
                    vh[row * 72 + c0 + q * 4 + e] = h;
                    vl[row * 72 + c0 + q * 4 + e] = __float2half_rn(x - __half2float(h));
                }
            }
        }
        __syncthreads();

        #pragma unroll
        for (int ks = 0; ks < 32; ks += 16) {
            wmma::fragment<wmma::matrix_a, 16, 16, 16, __half, wmma::row_major> ah[2], al[2];
            wmma::fragment<wmma::matrix_b, 16, 16, 16, __half, wmma::row_major> bh[2], bl[2];
            #pragma unroll
            for (int i = 0; i < 2; i++) {
                wmma::load_matrix_sync(ah[i], uh + (wm + i * 16) * 40 + ks, 40);
                wmma::load_matrix_sync(al[i], ul + (wm + i * 16) * 40 + ks, 40);
            }
            #pragma unroll
            for (int j = 0; j < 2; j++) {
                wmma::load_matrix_sync(bh[j], vh + ks * 72 + wn + j * 16, 72);
                wmma::load_matrix_sync(bl[j], vl + ks * 72 + wn + j * 16, 72);
            }
            #pragma unroll
            for (int i = 0; i < 2; i++)
                #pragma unroll
                for (int j = 0; j < 2; j++) {
                    wmma::mma_sync(acc[i][j], ah[i], bh[j], acc[i][j]);
                    wmma::mma_sync(acc[i][j], ah[i], bl[j], acc[i][j]);
                    wmma::mma_sync(acc[i][j], al[i], bh[j], acc[i][j]);
                }
        }
        __syncthreads();
    }

    float* wsf = (float*)ws;   // [64][68]
    #pragma unroll
    for (int i = 0; i < 2; i++)
        #pragma unroll
        for (int j = 0; j < 2; j++)
            wmma::store_matrix_sync(wsf + (wm + i * 16) * 68 + wn + j * 16,
                                    acc[i][j], 68, wmma::mem_row_major);
    __syncthreads();
    for (int e = tid; e < 64 * 64; e += 128) {
        int rr = e >> 6, cc = e & 63;
        g_wh[(size_t)(a0 + rr) * NN + b0 + cc] = __float2half_rn(wsf[rr * 68 + cc]);
    }
}

// ---------------- 4) out = x @ W^T, 1-term fp16 wmma, cp.async pipeline ----------------
#define GBK 32
#define XLD 40
#define TILE_H (128 * XLD)
#define STAGE_H (2 * TILE_H)     // xh, wh

__global__ void __launch_bounds__(256, 2) hgemm_kernel(float* __restrict__ C) {
    __shared__ __half sbuf[2 * STAGE_H];

    const int tid  = threadIdx.x;
    const int warp = tid >> 5;
    const int m0 = blockIdx.y * 128;
    const int n0 = blockIdx.x * 128;
    const int wm = (warp >> 2) * 64;
    const int wn = (warp & 3) * 32;

    wmma::fragment<wmma::accumulator, 16, 16, 16, float> acc[4][2];
    #pragma unroll
    for (int i = 0; i < 4; i++)
        #pragma unroll
        for (int j = 0; j < 2; j++) wmma::fill_fragment(acc[i][j], 0.0f);

    const int lr = tid >> 1;
    const int lh = (tid & 1) * 16;
    const __half* gx[2];
    gx[0] = g_xh + (size_t)(m0 + lr) * NN + lh;
    gx[1] = g_wh + (size_t)(n0 + lr) * NN + lh;
    const uint32_t sb0 = smem_u32(sbuf);
    const uint32_t dst_row = (uint32_t)(lr * XLD + lh) * 2;

    #define COPY_TILE(t, stg) do { \
        uint32_t _b = sb0 + (stg) * (STAGE_H * 2); \
        int _k = (t) * GBK; \
        _Pragma("unroll") \
        for (int _p = 0; _p < 2; _p++) { \
            uint32_t _d = _b + _p * (TILE_H * 2) + dst_row; \
            CP_ASYNC16(_d,      gx[_p] + _k); \
            CP_ASYNC16(_d + 16, gx[_p] + _k + 8); \
        } } while (0)

    COPY_TILE(0, 0);
    CP_COMMIT();

    for (int t = 0; t < NN / GBK; t++) {
        const int cur = t & 1;
        if (t + 1 < NN / GBK) { COPY_TILE(t + 1, cur ^ 1); CP_COMMIT(); CP_WAIT(1); }
        else                  { CP_WAIT(0); }
        __syncthreads();

        const __half* xh = sbuf + cur * STAGE_H;
        const __half* wh = xh + TILE_H;

        #pragma unroll
        for (int ks = 0; ks < GBK; ks += 16) {
            wmma::fragment<wmma::matrix_a, 16, 16, 16, __half, wmma::row_major> ah[4];
            wmma::fragment<wmma::matrix_b, 16, 16, 16, __half, wmma::col_major> bh[2];
            #pragma unroll
            for (int i = 0; i < 4; i++)
                wmma::load_matrix_sync(ah[i], xh + (wm + i * 16) * XLD + ks, XLD);
            #pragma unroll
            for (int j = 0; j < 2; j++)
                wmma::load_matrix_sync(bh[j], wh + (wn + j * 16) * XLD + ks, XLD);
            #pragma unroll
            for (int i = 0; i < 4; i++)
                #pragma unroll
                for (int j = 0; j < 2; j++)
                    wmma::mma_sync(acc[i][j], ah[i], bh[j], acc[i][j]);
        }
        __syncthreads();
    }

    #pragma unroll
    for (int i = 0; i < 4; i++)
        #pragma unroll
        for (int j = 0; j < 2; j++)
            wmma::store_matrix_sync(&C[(size_t)(m0 + wm + i * 16) * NN + n0 + wn + j * 16],
                                    acc[i][j], NN, wmma::mem_row_major);
}

// ---------------- launch ----------------
extern "C" void kernel_launch(void* const* d_in, const int* in_sizes, int n_in,
                              void* d_out, int out_size) {
    const float* x     = (const float*)d_in[0];
    const float* phiU  = (const float*)d_in[1];
    const float* dU    = (const float*)d_in[2];
    const float* phiV  = (const float*)d_in[3];
    const float* dV    = (const float*)d_in[4];
    const float* sigma = (const float*)d_in[5];
    float* out = (float*)d_out;

    const int recon_smem = 32 * RST * 4 + 1024 * 8 + (16 + 512 + 64) * 4;
    cudaFuncSetAttribute(reconstruct_kernel,
                         cudaFuncAttributeMaxDynamicSharedMemorySize, recon_smem);

    setup_cs_kernel<<<(2 * 512 * 512 + 255) / 256, 256>>>(phiU, phiV);
    setup_cq_kernel<<<(2 * 511 * 8 + 127) / 128, 128>>>();
    xsplit_kernel<<<32768 * 512 / (256 * 8), 256>>>(x);
    reconstruct_kernel<<<32, 256, recon_smem>>>(dU, dV, sigma);
    wgemm_kernel<<<dim3(8, 8), 128>>>();
    hgemm_kernel<<<dim3(NN / 128, 32768 / 128), 256>>>(out);
}

// round 17
// speedup vs baseline: 1.9781x; 1.7298x over previous
#include <cuda_runtime.h>
#include <cuda_fp16.h>
#include <mma.h>
#include <cstdint>
using namespace nvcuda;

#define NN 512
#define RST 516

// ---------------- device scratch (no allocations allowed) ----------------
__device__ __align__(16) float2 g_slot[2 * 512 * 512];   // (c,s) padded slots
__device__ __align__(16) float4 g_Cq[2 * 511 * 8];       // quarter cos-products
__device__ float g_T [2 * NN * NN];                      // compose ping
__device__ float g_T2[2 * NN * NN];                      // compose pong
__device__ float g_M [6 * NN * NN];                      // segment matrices k=1..3 x 2 mats
__device__ float g_U [NN * NN];
__device__ float g_Vs[NN * NN];
__device__ __align__(16) __half g_xh[32768 * 512];       // fp16 x
__device__ __align__(16) __half g_wh[NN * NN];           // fp16 W

__device__ __forceinline__ uint32_t smem_u32(const void* p) {
    uint32_t a;
    asm("{ .reg .u64 t; cvta.to.shared.u64 t, %1; cvt.u32.u64 %0, t; }" : "=r"(a) : "l"(p));
    return a;
}
#define CP_ASYNC16(sa, gp) \
    asm volatile("cp.async.ca.shared.global [%0], [%1], 16;" :: "r"(sa), "l"(gp) : "memory")
#define CP_COMMIT() asm volatile("cp.async.commit_group;" ::: "memory")
#define CP_WAIT(n)  asm volatile("cp.async.wait_group %0;" :: "n"(n) : "memory")

// ---------------- 1) cos/sin precompute into padded slots ----------------
__global__ void setup_cs_kernel(const float* __restrict__ phiU,
                                const float* __restrict__ phiV) {
    int tid = blockIdx.x * blockDim.x + threadIdx.x;
    if (tid >= 2 * 512 * 512) return;
    int mat = tid >> 18;
    int r   = tid & 262143;
    int i   = r >> 9;
    int m   = r & 511;
    float c = 1.0f, s = 0.0f;
    if (m < 511 - i) {
        int k = i * 511 - (i * (i - 1)) / 2 + m;
        float ph = mat ? __ldg(&phiV[k]) : __ldg(&phiU[k]);
        sincosf(ph, &s, &c);
    }
    g_slot[tid] = make_float2(c, s);
}

// ---------------- 1a) per-(pivot,warp) quarter cos-products ----------------
__global__ void setup_cq_kernel() {
    int t = blockIdx.x * blockDim.x + threadIdx.x;
    if (t >= 2 * 511 * 8) return;
    int mat = t / (511 * 8);
    int r   = t % (511 * 8);
    int i   = r >> 3;
    int w   = r & 7;
    int B   = (i >> 6) << 6;
    int LC  = ((511 - B + 63) >> 6) << 3;
    int m0  = w * LC;
    const float2* base = g_slot + (long)mat * 262144 + (long)i * 512 + m0;
    float4 c4;
    #pragma unroll
    for (int qt = 0; qt < 4; qt++) {
        float p = 1.0f;
        for (int k = qt * (LC / 4); k < (qt + 1) * (LC / 4); k++)
            p *= __ldg(&base[k]).x;
        ((float*)&c4)[qt] = p;
    }
    g_Cq[t] = c4;
}

// ---------------- 1b) x -> fp16 ----------------
__global__ void xsplit_kernel(const float* __restrict__ x) {
    int i = (blockIdx.x * 256 + threadIdx.x) * 8;
    float4 v0 = *(const float4*)(x + i);
    float4 v1 = *(const float4*)(x + i + 4);
    __half h[8];
    #pragma unroll
    for (int e = 0; e < 8; e++) {
        float f = (e < 4) ? ((const float*)&v0)[e] : ((const float*)&v1)[e - 4];
        h[e] = __float2half_rn(f);
    }
    *(uint4*)(g_xh + i) = *(uint4*)h;
}

// ---------------- 2) Givens-mesh reconstruction (segmented) ----------------
// do_block is IDENTICAL to the round-16 verified version.
template<int LC>
__device__ __forceinline__ void do_block(
    int B, int Bend, int w, int lane,
    float* __restrict__ myc, float2* __restrict__ ring0,
    float* __restrict__ Csh, float* __restrict__ Dsh, float* __restrict__ A0sh,
    const float4* __restrict__ slotf4, const float4* __restrict__ gCq)
{
    const int m0  = w * LC;
    const int f40 = m0 >> 1;
    const bool lact = lane < (LC / 2);
    const int fidx = f40 + lane;
    constexpr int Q = LC / 8;

    float v[LC];
    #pragma unroll
    for (int k = 0; k < LC; k++) v[k] = myc[511 - m0 - k];

    float4 pf, pf2;
    {
        float4* rw = (float4*)(ring0 + (B & 1) * 512);
        if (lact) {
            rw[fidx] = __ldg(slotf4 + B * 256 + fidx);
            int i1 = (B + 1 <= 510) ? B + 1 : 510;
            int i2 = (B + 2 <= 510) ? B + 2 : 510;
            pf  = __ldg(slotf4 + i1 * 256 + fidx);
            pf2 = __ldg(slotf4 + i2 * 256 + fidx);
        }
        __syncwarp();
    }

    for (int i = B; i < Bend; i++) {
        const int par = i & 1;
        const int L = 511 - i;
        const float4* rf = (const float4*)(ring0 + par * 512) + f40;
        const float4 cq = __ldg(&gCq[i * 8 + w]);

        if (i == B && w == 7) A0sh[par * 32 + lane] = myc[B];

        float D0 = 0.f, D1 = 0.f, D2 = 0.f, D3 = 0.f;
        #pragma unroll
        for (int q = 0; q < Q; q++) {
            float4 ra = rf[q], rb = rf[Q + q], rc = rf[2 * Q + q], rd = rf[3 * Q + q];
            D0 = fmaf(ra.x, D0, ra.y * v[2 * q]);
            D1 = fmaf(rb.x, D1, rb.y * v[2 * (Q + q)]);
            D2 = fmaf(rc.x, D2, rc.y * v[2 * (2 * Q + q)]);
            D3 = fmaf(rd.x, D3, rd.y * v[2 * (3 * Q + q)]);
            D0 = fmaf(ra.z, D0, ra.w * v[2 * q + 1]);
            D1 = fmaf(rb.z, D1, rb.w * v[2 * (Q + q) + 1]);
            D2 = fmaf(rc.z, D2, rc.w * v[2 * (2 * Q + q) + 1]);
            D3 = fmaf(rd.z, D3, rd.w * v[2 * (3 * Q + q) + 1]);
        }
        const float C0 = cq.x, C1 = cq.y, C2 = cq.z, C3 = cq.w;
        const float C01 = C0 * C1, D01 = fmaf(C1, D0, D1);
        const float C23 = C2 * C3, D23 = fmaf(C3, D2, D3);
        const float Cw = C01 * C23;
        const float Dw = fmaf(C23, D01, D23);

        if (lane == 0) Csh[par * 8 + w] = Cw;
        Dsh[par * 256 + w * 32 + lane] = Dw;

        if (i + 1 < Bend) {
            __syncwarp();
            float4* rw = (float4*)(ring0 + (par ^ 1) * 512);
            if (lact) {
                rw[fidx] = pf;
                pf = pf2;
                int nx = (i + 3 <= 510) ? i + 3 : 510;
                pf2 = __ldg(slotf4 + nx * 256 + fidx);
            }
        }

        __syncthreads();

        float A = A0sh[par * 32 + lane];
        #pragma unroll 7
        for (int kk = 0; kk < w; kk++)
            A = fmaf(Csh[par * 8 + kk], A, -Dsh[par * 256 + kk * 32 + lane]);
        if (w == 7) myc[i] = fmaf(Cw, A, -Dw);

        float A0c = A;
        float A1c = fmaf(C0, A, -D0);
        float A2c = fmaf(C01, A, -D01);
        const float C012 = C01 * C2;
        const float D012 = fmaf(C2, D01, D2);
        float A3c = fmaf(C012, A, -D012);
        #pragma unroll
        for (int q = 0; q < Q; q++) {
            float4 ra = rf[q], rb = rf[Q + q], rc = rf[2 * Q + q], rd = rf[3 * Q + q];
            { float u = v[2 * q];               float t = ra.y * u;
              v[2 * q]               = fmaf(ra.y, A0c, ra.x * u); A0c = fmaf(ra.x, A0c, -t); }
            { float u = v[2 * (Q + q)];         float t = rb.y * u;
              v[2 * (Q + q)]         = fmaf(rb.y, A1c, rb.x * u); A1c = fmaf(rb.x, A1c, -t); }
            { float u = v[2 * (2 * Q + q)];     float t = rc.y * u;
              v[2 * (2 * Q + q)]     = fmaf(rc.y, A2c, rc.x * u); A2c = fmaf(rc.x, A2c, -t); }
            { float u = v[2 * (3 * Q + q)];     float t = rd.y * u;
              v[2 * (3 * Q + q)]     = fmaf(rd.y, A3c, rd.x * u); A3c = fmaf(rd.x, A3c, -t); }
            { float u = v[2 * q + 1];           float t = ra.w * u;
              v[2 * q + 1]           = fmaf(ra.w, A0c, ra.z * u); A0c = fmaf(ra.z, A0c, -t); }
            { float u = v[2 * (Q + q) + 1];     float t = rb.w * u;
              v[2 * (Q + q) + 1]     = fmaf(rb.w, A1c, rb.z * u); A1c = fmaf(rb.z, A1c, -t); }
            { float u = v[2 * (2 * Q + q) + 1]; float t = rc.w * u;
              v[2 * (2 * Q + q) + 1] = fmaf(rc.w, A2c, rc.z * u); A2c = fmaf(rc.z, A2c, -t); }
            { float u = v[2 * (3 * Q + q) + 1]; float t = rd.w * u;
              v[2 * (3 * Q + q) + 1] = fmaf(rd.w, A3c, rd.z * u); A3c = fmaf(rd.z, A3c, -t); }
        }

        if (i + 1 < Bend) {
            int idx = (L - 1) - m0;
            if (idx >= 0 && idx < LC) {
                float val = 0.f;
                #pragma unroll
                for (int k = 0; k < LC; k++) if (k == idx) val = v[k];
                A0sh[((i + 1) & 1) * 32 + lane] = val;
            }
        }
    }

    #pragma unroll
    for (int k = 0; k < LC; k++)
        if (m0 + k <= 511 - Bend) myc[511 - m0 - k] = v[k];
}

// 80 CTAs: mat(2) x {seg0:16, seg1:12, seg2:8, seg3:4} column groups.
// Segment k covers pivots [128k, min(128(k+1),511)), matrix block rows/cols >= 128k.
__global__ void __launch_bounds__(256) reconstruct_kernel() {
    extern __shared__ float sm[];
    float*  cols  = sm;
    float2* ring0 = (float2*)(sm + 32 * RST);
    float*  Csh   = (float*)(ring0 + 1024);
    float*  Dsh   = Csh + 16;
    float*  A0sh  = Dsh + 512;

    const int b   = blockIdx.x;
    const int mat = b / 40;
    const int rr  = b - mat * 40;
    int seg, cg;
    if (rr < 16)      { seg = 0; cg = rr; }
    else if (rr < 28) { seg = 1; cg = rr - 16; }
    else if (rr < 36) { seg = 2; cg = rr - 28; }
    else              { seg = 3; cg = rr - 36; }
    const int r0 = seg << 7;
    const int nk = 512 - r0;
    const int segEnd = (seg == 3) ? 511 : (r0 + 128);

    const int tid  = threadIdx.x;
    const int w    = tid >> 5;
    const int lane = tid & 31;
    const int col  = r0 + (cg << 5) + lane;

    const float4* slotf4 = (const float4*)(g_slot + mat * 262144);
    const float4* gCq    = g_Cq + (long)mat * 511 * 8;
    float* myc = cols + lane * RST;
    float* outbuf = (seg == 0) ? (g_T + (size_t)mat * 262144)
                               : (g_M + (size_t)(mat * 3 + seg - 1) * 262144);

    // identity init on rows [r0, 512)
    const int rw8 = nk >> 3;   // rows per warp: 64/48/32/16
    for (int r = r0 + w * rw8; r < r0 + (w + 1) * rw8; r += 4) {
        float4 z = make_float4(0.f, 0.f, 0.f, 0.f);
        if (col >= r && col < r + 4) ((float*)&z)[col - r] = 1.0f;
        *(float4*)&myc[r] = z;
    }

    for (int B = r0; B < segEnd; B += 64) {
        const int Bend = (B + 64 < segEnd) ? B + 64 : segEnd;
        const int LC = ((511 - B + 63) >> 6) << 3;
        __syncthreads();
        switch (LC) {
            case 64: do_block<64>(B, Bend, w, lane, myc, ring0, Csh, Dsh, A0sh, slotf4, gCq); break;
            case 56: do_block<56>(B, Bend, w, lane, myc, ring0, Csh, Dsh, A0sh, slotf4, gCq); break;
            case 48: do_block<48>(B, Bend, w, lane, myc, ring0, Csh, Dsh, A0sh, slotf4, gCq); break;
            case 40: do_block<40>(B, Bend, w, lane, myc, ring0, Csh, Dsh, A0sh, slotf4, gCq); break;
            case 32: do_block<32>(B, Bend, w, lane, myc, ring0, Csh, Dsh, A0sh, slotf4, gCq); break;
            case 24: do_block<24>(B, Bend, w, lane, myc, ring0, Csh, Dsh, A0sh, slotf4, gCq); break;
            case 16: do_block<16>(B, Bend, w, lane, myc, ring0, Csh, Dsh, A0sh, slotf4, gCq); break;
            default: do_block< 8>(B, Bend, w, lane, myc, ring0, Csh, Dsh, A0sh, slotf4, gCq); break;
        }
    }
    __syncthreads();

    // raw segment writeback, rows [r0, 512)
    for (int r = r0 + w * rw8; r < r0 + (w + 1) * rw8; r++)
        outbuf[(size_t)r * NN + col] = myc[r];
}

// ---------------- 2b) compose: Tout = S_k * Tin  (rows < r0 copied) ----------------
// GEMM part: Tout[a][b] = sum_{q=r0}^{511} M[a][q] * Tin[q][b], 3-term fp16.
__global__ void __launch_bounds__(128) compose_kernel(int r0, int kidx,
                                                      const float* __restrict__ Tin_g,
                                                      float* __restrict__ Tout_g) {
    const int mat = blockIdx.z;
    const float* Msrc = g_M + (size_t)(mat * 3 + kidx) * 262144;
    const float* Tin  = Tin_g + (size_t)mat * 262144;
    float* Tout = Tout_g + (size_t)mat * 262144;

    const int tid  = threadIdx.x;
    const int a0 = blockIdx.y * 64;
    const int b0 = blockIdx.x * 64;

    if (a0 < r0) {   // copy tile
        for (int e = tid; e < 64 * 16; e += 128) {
            int r = e >> 4, c4 = (e & 15) << 2;
            *(float4*)&Tout[(size_t)(a0 + r) * NN + b0 + c4] =
                *(const float4*)&Tin[(size_t)(a0 + r) * NN + b0 + c4];
        }
        return;
    }

    __shared__ __align__(16) char ws[20480];
    __half* uh = (__half*)ws;
    __half* ul = uh + 64 * 40;
    __half* vh = ul + 64 * 40;
    __half* vl = vh + 32 * 72;

    const int warp = tid >> 5;
    const int wm = (warp >> 1) * 32;
    const int wn = (warp & 1) * 32;

    wmma::fragment<wmma::accumulator, 16, 16, 16, float> acc[2][2];
    #pragma unroll
    for (int i = 0; i < 2; i++)
        #pragma unroll
        for (int j = 0; j < 2; j++) wmma::fill_fragment(acc[i][j], 0.0f);

    for (int kt = r0; kt < NN; kt += 32) {
        {
            int row = tid >> 1, c0 = (tid & 1) * 16;
            const float* src = Msrc + (size_t)(a0 + row) * NN + kt + c0;
            #pragma unroll
            for (int q = 0; q < 4; q++) {
                float4 f = *(const float4*)(src + q * 4);
                #pragma unroll
                for (int e = 0; e < 4; e++) {
                    float x = ((const float*)&f)[e];
                    __half h = __float2half_rn(x);
                    uh[row * 40 + c0 + q * 4 + e] = h;
                    ul[row * 40 + c0 + q * 4 + e] = __float2half_rn(x - __half2float(h));
                }
            }
        }
        {
            int row = tid >> 2, c0 = (tid & 3) * 16;
            const float* src = Tin + (size_t)(kt + row) * NN + b0 + c0;
            #pragma unroll
            for (int q = 0; q < 4; q++) {
                float4 f = *(const float4*)(src + q * 4);
                #pragma unroll
                for (int e = 0; e < 4; e++) {
                    float x = ((const float*)&f)[e];
                    __half h = __float2half_rn(x);
                    vh[row * 72 + c0 + q * 4 + e] = h;
                    vl[row * 72 + c0 + q * 4 + e] = __float2half_rn(x - __half2float(h));
                }
            }
        }
        __syncthreads();

        #pragma unroll
        for (int ks = 0; ks < 32; ks += 16) {
            wmma::fragment<wmma::matrix_a, 16, 16, 16, __half, wmma::row_major> ah[2], al[2];
            wmma::fragment<wmma::matrix_b, 16, 16, 16, __half, wmma::row_major> bh[2], bl[2];
            #pragma unroll
            for (int i = 0; i < 2; i++) {
                wmma::load_matrix_sync(ah[i], uh + (wm + i * 16) * 40 + ks, 40);
                wmma::load_matrix_sync(al[i], ul + (wm + i * 16) * 40 + ks, 40);
            }
            #pragma unroll
            for (int j = 0; j < 2; j++) {
                wmma::load_matrix_sync(bh[j], vh + ks * 72 + wn + j * 16, 72);
                wmma::load_matrix_sync(bl[j], vl + ks * 72 + wn + j * 16, 72);
            }
            #pragma unroll
            for (int i = 0; i < 2; i++)
                #pragma unroll
                for (int j = 0; j < 2; j++) {
                    wmma::mma_sync(acc[i][j], ah[i], bh[j], acc[i][j]);
                    wmma::mma_sync(acc[i][j], ah[i], bl[j], acc[i][j]);
                    wmma::mma_sync(acc[i][j], al[i], bh[j], acc[i][j]);
                }
        }
        __syncthreads();
    }

    float* wsf = (float*)ws;
    #pragma unroll
    for (int i = 0; i < 2; i++)
        #pragma unroll
        for (int j = 0; j < 2; j++)
            wmma::store_matrix_sync(wsf + (wm + i * 16) * 68 + wn + j * 16,
                                    acc[i][j], 68, wmma::mem_row_major);
    __syncthreads();
    for (int e = tid; e < 64 * 64; e += 128) {
        int rrr = e >> 6, ccc = e & 63;
        Tout[(size_t)(a0 + rrr) * NN + b0 + ccc] = wsf[rrr * 68 + ccc];
    }
}

// ---------------- 2c) diag scaling: g_U, g_Vs from composed R ----------------
__global__ void scale_kernel(const float* __restrict__ dU, const float* __restrict__ dV,
                             const float* __restrict__ sigma) {
    int tid = blockIdx.x * 256 + threadIdx.x;      // over 2*512*512/4 float4s
    int mat = tid >> 16;
    int r   = (tid & 65535);
    int a   = r >> 7;
    int c4  = (r & 127) << 2;
    float4 v = *(const float4*)&g_T2[(size_t)mat * 262144 + a * NN + c4];
    float sc = mat ? __ldg(&sigma[a]) * __ldg(&dV[a]) : __ldg(&dU[a]);
    v.x *= sc; v.y *= sc; v.z *= sc; v.w *= sc;
    if (mat == 0) *(float4*)&g_U [a * NN + c4] = v;
    else          *(float4*)&g_Vs[a * NN + c4] = v;
}

// ---------------- 3) W = U @ Vs via 3-term fp16 wmma, fp16 epilogue ----------------
__global__ void __launch_bounds__(128) wgemm_kernel() {
    __shared__ __align__(16) char ws[20480];
    __half* uh = (__half*)ws;
    __half* ul = uh + 64 * 40;
    __half* vh = ul + 64 * 40;
    __half* vl = vh + 32 * 72;

    const int tid  = threadIdx.x;
    const int warp = tid >> 5;
    const int a0 = blockIdx.y * 64;
    const int b0 = blockIdx.x * 64;
    const int wm = (warp >> 1) * 32;
    const int wn = (warp & 1) * 32;

    wmma::fragment<wmma::accumulator, 16, 16, 16, float> acc[2][2];
    #pragma unroll
    for (int i = 0; i < 2; i++)
        #pragma unroll
        for (int j = 0; j < 2; j++) wmma::fill_fragment(acc[i][j], 0.0f);

    for (int kt = 0; kt < NN; kt += 32) {
        {
            int row = tid >> 1, c0 = (tid & 1) * 16;
            const float* src = g_U + (size_t)(a0 + row) * NN + kt + c0;
            #pragma unroll
            for (int q = 0; q < 4; q++) {
                float4 f = *(const float4*)(src + q * 4);
                #pragma unroll
                for (int e = 0; e < 4; e++) {
                    float x = ((const float*)&f)[e];
                    __half h = __float2half_rn(x);
                    uh[row * 40 + c0 + q * 4 + e] = h;
                    ul[row * 40 + c0 + q * 4 + e] = __float2half_rn(x - __half2float(h));
                }
            }
        }
        {
            int row = tid >> 2, c0 = (tid & 3) * 16;
            const float* src = g_Vs + (size_t)(kt + row) * NN + b0 + c0;
            #pragma unroll
            for (int q = 0; q < 4; q++) {
                float4 f = *(const float4*)(src + q * 4);
                #pragma unroll
                for (int e = 0; e < 4; e++) {
                    float x = ((const float*)&f)[e];
                    __half h = __float2half_rn(x);
                    vh[row * 72 + c0 + q * 4 + e] = h;
                    vl[row * 72 + c0 + q * 4 + e] = __float2half_rn(x - __half2float(h));
                }
            }
        }
        __syncthreads();

        #pragma unroll
        for (int ks = 0; ks < 32; ks += 16) {
            wmma::fragment<wmma::matrix_a, 16, 16, 16, __half, wmma::row_major> ah[2], al[2];
            wmma::fragment<wmma::matrix_b, 16, 16, 16, __half, wmma::row_major> bh[2], bl[2];
            #pragma unroll
            for (int i = 0; i < 2; i++) {
                wmma::load_matrix_sync(ah[i], uh + (wm + i * 16) * 40 + ks, 40);
                wmma::load_matrix_sync(al[i], ul + (wm + i * 16) * 40 + ks, 40);
            }
            #pragma unroll
            for (int j = 0; j < 2; j++) {
                wmma::load_matrix_sync(bh[j], vh + ks * 72 + wn + j * 16, 72);
                wmma::load_matrix_sync(bl[j], vl + ks * 72 + wn + j * 16, 72);
            }
            #pragma unroll
            for (int i = 0; i < 2; i++)
                #pragma unroll
                for (int j = 0; j < 2; j++) {
                    wmma::mma_sync(acc[i][j], ah[i], bh[j], acc[i][j]);
                    wmma::mma_sync(acc[i][j], ah[i], bl[j], acc[i][j]);
                    wmma::mma_sync(acc[i][j], al[i], bh[j], acc[i][j]);
                }
        }
        __syncthreads();
    }

    float* wsf = (float*)ws;
    #pragma unroll
    for (int i = 0; i < 2; i++)
        #pragma unroll
        for (int j = 0; j < 2; j++)
            wmma::store_matrix_sync(wsf + (wm + i * 16) * 68 + wn + j * 16,
                                    acc[i][j], 68, wmma::mem_row_major);
    __syncthreads();
    for (int e = tid; e < 64 * 64; e += 128) {
        int rr = e >> 6, cc = e & 63;
        g_wh[(size_t)(a0 + rr) * NN + b0 + cc] = __float2half_rn(wsf[rr * 68 + cc]);
    }
}

// ---------------- 4) out = x @ W^T, 1-term fp16 wmma, cp.async pipeline ----------------
#define GBK 32
#define XLD 40
#define TILE_H (128 * XLD)
#define STAGE_H (2 * TILE_H)

__global__ void __launch_bounds__(256, 2) hgemm_kernel(float* __restrict__ C) {
    __shared__ __half sbuf[2 * STAGE_H];

    const int tid  = threadIdx.x;
    const int warp = tid >> 5;
    const int m0 = blockIdx.y * 128;
    const int n0 = blockIdx.x * 128;
    const int wm = (warp >> 2) * 64;
    const int wn = (warp & 3) * 32;

    wmma::fragment<wmma::accumulator, 16, 16, 16, float> acc[4][2];
    #pragma unroll
    for (int i = 0; i < 4; i++)
        #pragma unroll
        for (int j = 0; j < 2; j++) wmma::fill_fragment(acc[i][j], 0.0f);

    const int lr = tid >> 1;
    const int lh = (tid & 1) * 16;
    const __half* gx[2];
    gx[0] = g_xh + (size_t)(m0 + lr) * NN + lh;
    gx[1] = g_wh + (size_t)(n0 + lr) * NN + lh;
    const uint32_t sb0 = smem_u32(sbuf);
    const uint32_t dst_row = (uint32_t)(lr * XLD + lh) * 2;

    #define COPY_TILE(t, stg) do { \
        uint32_t _b = sb0 + (stg) * (STAGE_H * 2); \
        int _k = (t) * GBK; \
        _Pragma("unroll") \
        for (int _p = 0; _p < 2; _p++) { \
            uint32_t _d = _b + _p * (TILE_H * 2) + dst_row; \
            CP_ASYNC16(_d,      gx[_p] + _k); \
            CP_ASYNC16(_d + 16, gx[_p] + _k + 8); \
        } } while (0)

    COPY_TILE(0, 0);
    CP_COMMIT();

    for (int t = 0; t < NN / GBK; t++) {
        const int cur = t & 1;
        if (t + 1 < NN / GBK) { COPY_TILE(t + 1, cur ^ 1); CP_COMMIT(); CP_WAIT(1); }
        else                  { CP_WAIT(0); }
        __syncthreads();

        const __half* xh = sbuf + cur * STAGE_H;
        const __half* wh = xh + TILE_H;

        #pragma unroll
        for (int ks = 0; ks < GBK; ks += 16) {
            wmma::fragment<wmma::matrix_a, 16, 16, 16, __half, wmma::row_major> ah[4];
            wmma::fragment<wmma::matrix_b, 16, 16, 16, __half, wmma::col_major> bh[2];
            #pragma unroll
            for (int i = 0; i < 4; i++)
                wmma::load_matrix_sync(ah[i], xh + (wm + i * 16) * XLD + ks, XLD);
            #pragma unroll
            for (int j = 0; j < 2; j++)
                wmma::load_matrix_sync(bh[j], wh + (wn + j * 16) * XLD + ks, XLD);
            #pragma unroll
            for (int i = 0; i < 4; i++)
                #pragma unroll
                for (int j = 0; j < 2; j++)
                    wmma::mma_sync(acc[i][j], ah[i], bh[j], acc[i][j]);
        }
        __syncthreads();
    }

    #pragma unroll
    for (int i = 0; i < 4; i++)
        #pragma unroll
        for (int j = 0; j < 2; j++)
            wmma::store_matrix_sync(&C[(size_t)(m0 + wm + i * 16) * NN + n0 + wn + j * 16],
                                    acc[i][j], NN, wmma::mem_row_major);
}

// ---------------- launch ----------------
extern "C" void kernel_launch(void* const* d_in, const int* in_sizes, int n_in,
                              void* d_out, int out_size) {
    const float* x     = (const float*)d_in[0];
    const float* phiU  = (const float*)d_in[1];
    const float* dU    = (const float*)d_in[2];
    const float* phiV  = (const float*)d_in[3];
    const float* dV    = (const float*)d_in[4];
    const float* sigma = (const float*)d_in[5];
    float* out = (float*)d_out;

    const int recon_smem = 32 * RST * 4 + 1024 * 8 + (16 + 512 + 64) * 4;
    cudaFuncSetAttribute(reconstruct_kernel,
                         cudaFuncAttributeMaxDynamicSharedMemorySize, recon_smem);

    float* pT  = nullptr; float* pT2 = nullptr;
    cudaGetSymbolAddress((void**)&pT,  g_T);
    cudaGetSymbolAddress((void**)&pT2, g_T2);

    setup_cs_kernel<<<(2 * 512 * 512 + 255) / 256, 256>>>(phiU, phiV);
    setup_cq_kernel<<<(2 * 511 * 8 + 127) / 128, 128>>>();
    xsplit_kernel<<<32768 * 512 / (256 * 8), 256>>>(x);
    reconstruct_kernel<<<80, 256, recon_smem>>>();
    compose_kernel<<<dim3(8, 8, 2), 128>>>(128, 0, pT,  pT2);
    compose_kernel<<<dim3(8, 8, 2), 128>>>(256, 1, pT2, pT);
    compose_kernel<<<dim3(8, 8, 2), 128>>>(384, 2, pT,  pT2);
    scale_kernel<<<2 * 512 * 512 / 4 / 256, 256>>>(dU, dV, sigma);
    wgemm_kernel<<<dim3(8, 8), 128>>>();
    hgemm_kernel<<<dim3(NN / 128, 32768 / 128), 256>>>(out);
}